// round 11
// baseline (speedup 1.0000x reference)
#include <cuda_runtime.h>
#include <math.h>

#define NDIM    64
#define LD      65
#define NMAT    4096
#define NDOMS   8
#define MATSZ   (NDIM*NDIM)
#define BUF     (NDIM*LD)
#define MAXSWEEPS 8
#define EIG_EPS 1e-4f
#define EPS_C   1e-5f

// ---------------- device scratch ----------------
__device__ float g_bmsum [NDOMS*MATSZ];
__device__ float g_bm_sq [NDOMS*MATSZ];
__device__ float g_bm_isq[NDOMS*MATSZ];
__device__ float g_GT    [NDOMS*MATSZ];
__device__ float g_rm_isq[NDOMS*MATSZ];
__device__ float g_Bsq   [MATSZ];
__device__ float g_sumsq [NDOMS];
__device__ float g_cnt   [NDOMS];
__device__ float g_s     [NDOMS];
__device__ int   g_noBsq;
__device__ float g_XT [(size_t)NMAT*MATSZ];
__device__ float g_V3 [(size_t)NMAT*MATSZ];

// ---------------- helpers ----------------
__device__ __forceinline__ float blockReduceSum(float v) {
    __shared__ float red[8];
    const unsigned m = 0xffffffffu;
    #pragma unroll
    for (int o = 16; o; o >>= 1) v += __shfl_down_sync(m, v, o);
    if ((threadIdx.x & 31) == 0) red[threadIdx.x >> 5] = v;
    __syncthreads();
    if (threadIdx.x < 32) {
        float x = (threadIdx.x < 8) ? red[threadIdx.x] : 0.0f;
        #pragma unroll
        for (int o = 4; o; o >>= 1) x += __shfl_down_sync(m, x, o);
        if (threadIdx.x == 0) red[0] = x;
    }
    __syncthreads();
    float r = red[0];
    __syncthreads();
    return r;
}

__device__ __forceinline__ void g2s(const float* __restrict__ g, float* __restrict__ S) {
    const float4* g4 = (const float4*)g;
    for (int i = threadIdx.x; i < MATSZ/4; i += 256) {
        float4 v = g4[i];
        int r = i >> 4, c = (i & 15) << 2;
        float* d = S + r*LD + c;
        d[0]=v.x; d[1]=v.y; d[2]=v.z; d[3]=v.w;
    }
}
__device__ __forceinline__ void s2g(const float* __restrict__ S, float* __restrict__ g) {
    float4* g4 = (float4*)g;
    for (int i = threadIdx.x; i < MATSZ/4; i += 256) {
        int r = i >> 4, c = (i & 15) << 2;
        const float* s = S + r*LD + c;
        g4[i] = make_float4(s[0], s[1], s[2], s[3]);
    }
}

template<bool TRANSB>
__device__ __forceinline__ void mm64(const float* __restrict__ A,
                                     const float* __restrict__ B,
                                     float* __restrict__ C, int ldc) {
    const int tid = threadIdx.x;
    const int r0 = (tid >> 4) << 2;
    const int c0 = (tid & 15) << 2;
    float acc[4][4];
    #pragma unroll
    for (int i = 0; i < 4; i++)
        #pragma unroll
        for (int j = 0; j < 4; j++) acc[i][j] = 0.0f;
    #pragma unroll 4
    for (int k = 0; k < 64; k++) {
        float a0 = A[(r0+0)*LD + k];
        float a1 = A[(r0+1)*LD + k];
        float a2 = A[(r0+2)*LD + k];
        float a3 = A[(r0+3)*LD + k];
        float b0, b1, b2, b3;
        if (TRANSB) {
            b0 = B[(c0+0)*LD + k]; b1 = B[(c0+1)*LD + k];
            b2 = B[(c0+2)*LD + k]; b3 = B[(c0+3)*LD + k];
        } else {
            b0 = B[k*LD + c0+0]; b1 = B[k*LD + c0+1];
            b2 = B[k*LD + c0+2]; b3 = B[k*LD + c0+3];
        }
        acc[0][0] += a0*b0; acc[0][1] += a0*b1; acc[0][2] += a0*b2; acc[0][3] += a0*b3;
        acc[1][0] += a1*b0; acc[1][1] += a1*b1; acc[1][2] += a1*b2; acc[1][3] += a1*b3;
        acc[2][0] += a2*b0; acc[2][1] += a2*b1; acc[2][2] += a2*b2; acc[2][3] += a2*b3;
        acc[3][0] += a3*b0; acc[3][1] += a3*b1; acc[3][2] += a3*b2; acc[3][3] += a3*b3;
    }
    #pragma unroll
    for (int i = 0; i < 4; i++)
        #pragma unroll
        for (int j = 0; j < 4; j++)
            C[(size_t)(r0+i)*ldc + c0 + j] = acc[i][j];
}

// C = A^T * B (both smem, stride LD)
__device__ __forceinline__ void mm64_tA(const float* __restrict__ A,
                                        const float* __restrict__ B,
                                        float* __restrict__ C) {
    const int tid = threadIdx.x;
    const int r0 = (tid >> 4) << 2;
    const int c0 = (tid & 15) << 2;
    float acc[4][4];
    #pragma unroll
    for (int i = 0; i < 4; i++)
        #pragma unroll
        for (int j = 0; j < 4; j++) acc[i][j] = 0.0f;
    #pragma unroll 4
    for (int k = 0; k < 64; k++) {
        float a0 = A[k*LD + r0+0];
        float a1 = A[k*LD + r0+1];
        float a2 = A[k*LD + r0+2];
        float a3 = A[k*LD + r0+3];
        float b0 = B[k*LD + c0+0], b1 = B[k*LD + c0+1];
        float b2 = B[k*LD + c0+2], b3 = B[k*LD + c0+3];
        acc[0][0] += a0*b0; acc[0][1] += a0*b1; acc[0][2] += a0*b2; acc[0][3] += a0*b3;
        acc[1][0] += a1*b0; acc[1][1] += a1*b1; acc[1][2] += a1*b2; acc[1][3] += a1*b3;
        acc[2][0] += a2*b0; acc[2][1] += a2*b1; acc[2][2] += a2*b2; acc[2][3] += a2*b3;
        acc[3][0] += a3*b0; acc[3][1] += a3*b1; acc[3][2] += a3*b2; acc[3][3] += a3*b3;
    }
    #pragma unroll
    for (int i = 0; i < 4; i++)
        #pragma unroll
        for (int j = 0; j < 4; j++)
            C[(r0+i)*LD + c0 + j] = acc[i][j];
}

__device__ __forceinline__ void symmetrize(const float* __restrict__ S, float* __restrict__ D) {
    for (int i = threadIdx.x; i < MATSZ; i += 256) {
        int r = i >> 6, c = i & 63;
        D[r*LD+c] = 0.5f*(S[r*LD+c] + S[c*LD+r]);
    }
}

// ---- two-sided Jacobi (per-domain kernels; handles indefinite) ----
template<bool INITV>
__device__ void jacobi_eig(float* A, float* V, float tol) {
    const int tid  = threadIdx.x;
    const int warp = tid >> 5;
    const int lane = tid & 31;
    const unsigned FULL = 0xffffffffu;
    if (INITV) {
        for (int i = tid; i < MATSZ; i += 256) {
            int r = i >> 6, c = i & 63;
            V[r*LD+c] = (r == c) ? 1.0f : 0.0f;
        }
        __syncthreads();
    }
    for (int sw = 0; sw < MAXSWEEPS; sw++) {
        float offs = 0.0f, tots = 0.0f;
        for (int i = tid; i < MATSZ; i += 256) {
            int r = i >> 6, c = i & 63;
            float a = A[r*LD+c], a2 = a*a;
            tots += a2;
            if (r != c) offs += a2;
        }
        float offT = blockReduceSum(offs);
        float totT = blockReduceSum(tots);
        if (offT <= tol * totT + 1e-30f) break;

        for (int rd = 0; rd < 63; rd++) {
            const int x = (rd * 32) % 63;
            int myp = 0, myq = 0; float myc = 1.0f, mys = 0.0f;
            if (lane < 4) {
                const int slot = warp * 4 + lane;
                if (slot == 0) { myp = x; myq = 63; }
                else {
                    int a = x + slot; if (a >= 63) a -= 63;
                    int b = x - slot; if (b < 0)   b += 63;
                    myp = min(a, b); myq = max(a, b);
                }
                const float apq = A[myp*LD+myq];
                const float app = A[myp*LD+myp];
                const float aqq = A[myq*LD+myq];
                if (fabsf(apq) > 2e-7f * (fabsf(app) + fabsf(aqq))) {
                    const float tau = (aqq - app) / (2.0f * apq);
                    float t = 1.0f / (fabsf(tau) + sqrtf(1.0f + tau*tau));
                    if (tau < 0.0f) t = -t;
                    myc = rsqrtf(1.0f + t*t);
                    mys = t * myc;
                }
            }
            int pp[4], qq[4]; float cc[4], ssv[4];
            #pragma unroll
            for (int t = 0; t < 4; t++) {
                pp[t]  = __shfl_sync(FULL, myp, t);
                qq[t]  = __shfl_sync(FULL, myq, t);
                cc[t]  = __shfl_sync(FULL, myc, t);
                ssv[t] = __shfl_sync(FULL, mys, t);
            }
            #pragma unroll
            for (int t = 0; t < 4; t++) {
                const float c = cc[t], s = ssv[t];
                if (s != 0.0f) {
                    float* Ap = A + pp[t]*LD;
                    float* Aq = A + qq[t]*LD;
                    #pragma unroll
                    for (int kk = 0; kk < 2; kk++) {
                        const int k = lane + 32*kk;
                        const float ap = Ap[k], aq = Aq[k];
                        Ap[k] = c*ap - s*aq;
                        Aq[k] = s*ap + c*aq;
                    }
                }
            }
            __syncthreads();
            float* Ar0 = A + lane*LD;
            float* Vr0 = V + lane*LD;
            #pragma unroll
            for (int t = 0; t < 4; t++) {
                const float c = cc[t], s = ssv[t];
                if (s != 0.0f) {
                    const int p = pp[t], q = qq[t];
                    #pragma unroll
                    for (int kk = 0; kk < 2; kk++) {
                        float* Ar = Ar0 + 32*LD*kk;
                        float* Vr = Vr0 + 32*LD*kk;
                        const float ap = Ar[p], aq = Ar[q];
                        Ar[p] = c*ap - s*aq;
                        Ar[q] = s*ap + c*aq;
                        const float vp = Vr[p], vq = Vr[q];
                        Vr[p] = c*vp - s*vq;
                        Vr[q] = s*vp + c*vq;
                    }
                }
            }
            __syncthreads();
        }
    }
}

// ---- register-resident one-sided Jacobi (SPD), Brent-Luk odd-even ordering ----
// Bm (smem, stride LD): SPD matrix in; on exit Bm columns = ORTHONORMAL eigenvectors
// (arbitrary order/sign), lam[j] = eigenvalue of column j.
// 32 workers x 8 threads; each worker holds 2 columns in registers.
// A-rounds: intra-worker (register-only). B-rounds: neighbor exchange via shfl
// (warp-internal) or a tiny smem staging buffer (7 warp boundaries).
__device__ void jacobi_os_reg(float* Bm, float* lam) {
    __shared__ float xb[7*64];
    __shared__ float xbn[8];
    __shared__ int chg;
    const int tid = threadIdx.x;
    const int w   = tid >> 3;        // worker 0..31
    const int g   = tid & 7;
    const int ww  = w & 3;           // worker within warp
    const int wp  = w >> 2;          // warp id
    const unsigned FULL = 0xffffffffu;
    float P[8], Q[8], R[8], xs[8];
    #pragma unroll
    for (int i = 0; i < 8; i++) {
        int k = g + 8*i;
        P[i] = Bm[k*LD + 2*w];
        Q[i] = Bm[k*LD + 2*w + 1];
    }
    if (tid == 0) chg = 0;
    __syncthreads();
    for (int sw = 0; sw < MAXSWEEPS; sw++) {
        // fresh carried norms each sweep
        float nP = 0.0f, nQ = 0.0f;
        #pragma unroll
        for (int i = 0; i < 8; i++) { nP += P[i]*P[i]; nQ += Q[i]*Q[i]; }
        #pragma unroll
        for (int o = 4; o; o >>= 1) { nP += __shfl_xor_sync(FULL, nP, o); nQ += __shfl_xor_sync(FULL, nQ, o); }
        for (int half = 0; half < 32; half++) {
            // ---------- A round: pair (2w, 2w+1), register-only ----------
            float d = 0.0f;
            #pragma unroll
            for (int i = 0; i < 8; i++) d += P[i]*Q[i];
            #pragma unroll
            for (int o = 4; o; o >>= 1) d += __shfl_xor_sync(FULL, d, o);
            if (d*d > 4e-14f * nP * nQ) {
                float tau = (nQ - nP) / (2.0f * d);
                float t = 1.0f / (fabsf(tau) + sqrtf(1.0f + tau*tau));
                if (tau < 0.0f) t = -t;
                float c = rsqrtf(1.0f + t*t), s = t*c;
                #pragma unroll
                for (int i = 0; i < 8; i++) {
                    float x = P[i], y = Q[i];
                    P[i] = s*x + c*y;        // y' -> pos 2w   (swap)
                    Q[i] = c*x - s*y;        // x' -> pos 2w+1
                }
                float tcs = 2.0f*c*s*d;
                float nPn = s*s*nP + tcs + c*c*nQ;
                float nQn = c*c*nP - tcs + s*s*nQ;
                nP = nPn; nQ = nQn;
                if (g == 0) chg = 1;
            } else {
                #pragma unroll
                for (int i = 0; i < 8; i++) { float x = P[i]; P[i] = Q[i]; Q[i] = x; }
                float x = nP; nP = nQ; nQ = x;
            }
            // ---------- B round: pair (2w+1, 2w+2) ----------
            // stage 1: obtain R = P of worker w+1
            if (ww == 0 && wp > 0) {
                #pragma unroll
                for (int i = 0; i < 8; i++) xb[(wp-1)*64 + g + 8*i] = P[i];
                if (g == 0) xbn[wp-1] = nP;
            }
            __syncthreads();
            float nR;
            #pragma unroll
            for (int i = 0; i < 8; i++) R[i] = __shfl_down_sync(FULL, P[i], 8);
            nR = __shfl_down_sync(FULL, nP, 8);
            if (ww == 3 && wp < 7) {
                #pragma unroll
                for (int i = 0; i < 8; i++) R[i] = xb[wp*64 + g + 8*i];
                nR = xbn[wp];
            }
            const bool doPair = (w <= 30);
            float d2 = 0.0f;
            #pragma unroll
            for (int i = 0; i < 8; i++) d2 += Q[i]*R[i];
            #pragma unroll
            for (int o = 4; o; o >>= 1) d2 += __shfl_xor_sync(FULL, d2, o);
            float nXs;
            if (doPair && d2*d2 > 4e-14f * nQ * nR) {
                float tau = (nR - nQ) / (2.0f * d2);
                float t = 1.0f / (fabsf(tau) + sqrtf(1.0f + tau*tau));
                if (tau < 0.0f) t = -t;
                float c = rsqrtf(1.0f + t*t), s = t*c;
                #pragma unroll
                for (int i = 0; i < 8; i++) {
                    float x = Q[i], y = R[i];
                    xs[i] = c*x - s*y;       // x' -> pos 2w+2 (send to w+1)
                    Q[i]  = s*x + c*y;       // y' -> pos 2w+1
                }
                float tcs = 2.0f*c*s*d2;
                nXs = c*c*nQ - tcs + s*s*nR;
                nQ  = s*s*nQ + tcs + c*c*nR;
                if (g == 0) chg = 1;
            } else {
                #pragma unroll
                for (int i = 0; i < 8; i++) xs[i] = Q[i];
                nXs = nQ;
                if (doPair) {
                    #pragma unroll
                    for (int i = 0; i < 8; i++) Q[i] = R[i];
                    nQ = nR;
                }
            }
            // stage 2: send xs -> worker w+1's new P
            if (ww == 3 && wp < 7) {
                #pragma unroll
                for (int i = 0; i < 8; i++) xb[wp*64 + g + 8*i] = xs[i];
                if (g == 0) xbn[wp] = nXs;
            }
            __syncthreads();
            #pragma unroll
            for (int i = 0; i < 8; i++) R[i] = __shfl_up_sync(FULL, xs[i], 8);
            nR = __shfl_up_sync(FULL, nXs, 8);
            if (ww == 0 && wp > 0) {
                #pragma unroll
                for (int i = 0; i < 8; i++) R[i] = xb[(wp-1)*64 + g + 8*i];
                nR = xbn[wp-1];
            }
            if (w >= 1) {
                #pragma unroll
                for (int i = 0; i < 8; i++) P[i] = R[i];
                nP = nR;
            }
        }
        int c = chg;
        __syncthreads();
        if (c == 0) break;
        if (tid == 0) chg = 0;
        __syncthreads();
    }
    // normalized eigenvector columns + eigenvalues (fresh norms)
    float a = 0.0f, b = 0.0f;
    #pragma unroll
    for (int i = 0; i < 8; i++) { a += P[i]*P[i]; b += Q[i]*Q[i]; }
    #pragma unroll
    for (int o = 4; o; o >>= 1) { a += __shfl_xor_sync(FULL, a, o); b += __shfl_xor_sync(FULL, b, o); }
    float la = sqrtf(a), lb = sqrtf(b);
    float ia = 1.0f / fmaxf(la, 1e-20f), ib = 1.0f / fmaxf(lb, 1e-20f);
    #pragma unroll
    for (int i = 0; i < 8; i++) {
        int k = g + 8*i;
        Bm[k*LD + 2*w]     = P[i]*ia;
        Bm[k*LD + 2*w + 1] = Q[i]*ib;
    }
    if (g == 0) { lam[2*w] = la; lam[2*w+1] = lb; }
    __syncthreads();
}

// ---------------- kernels ----------------
__global__ void kzero_kernel() {
    int i = blockIdx.x * blockDim.x + threadIdx.x;
    int stride = gridDim.x * blockDim.x;
    for (int j = i; j < NDOMS*MATSZ; j += stride) { g_bmsum[j] = 0.0f; g_GT[j] = 0.0f; }
    if (i < NDOMS) g_sumsq[i] = 0.0f;
}

__global__ void __launch_bounds__(256) k1_kernel(const float* __restrict__ X,
                                                 const int* __restrict__ dd) {
    __shared__ int sdom[128];
    const int e  = blockIdx.x * 256 + threadIdx.x;
    const int n0 = blockIdx.y * 128;
    if (threadIdx.x < 128) sdom[threadIdx.x] = dd[n0 + threadIdx.x];
    __syncthreads();
    float acc[NDOMS];
    #pragma unroll
    for (int k = 0; k < NDOMS; k++) acc[k] = 0.0f;
    for (int m = 0; m < 128; m++) {
        float x = X[(size_t)(n0 + m) * MATSZ + e];
        int dom = sdom[m];
        #pragma unroll
        for (int k = 0; k < NDOMS; k++) acc[k] += (dom == k) ? x : 0.0f;
    }
    #pragma unroll
    for (int k = 0; k < NDOMS; k++) atomicAdd(&g_bmsum[k*MATSZ + e], acc[k]);
}

__global__ void __launch_bounds__(256) k2_kernel(const int* __restrict__ dd) {
    extern __shared__ float sm[];
    float* SX = sm; float* SA = sm + BUF; float* SV = sm + 2*BUF;
    __shared__ float sl[64];
    const int dom = blockIdx.x, tid = threadIdx.x;

    float loc = 0.0f;
    for (int i = tid; i < NMAT; i += 256) loc += (dd[i] == dom) ? 1.0f : 0.0f;
    float cnt  = blockReduceSum(loc);
    float cntf = fmaxf(cnt, 1.0f);
    if (tid == 0) g_cnt[dom] = cntf;

    for (int i = tid; i < MATSZ; i += 256) {
        int r = i >> 6, c = i & 63;
        SX[r*LD+c] = g_bmsum[dom*MATSZ + i] / cntf;
    }
    __syncthreads();
    symmetrize(SX, SA);
    __syncthreads();
    jacobi_eig<true>(SA, SV, 1e-8f);
    if (tid < 64) sl[tid] = fmaxf(SA[tid*LD+tid], EIG_EPS);
    __syncthreads();
    for (int i = tid; i < MATSZ; i += 256) {
        int r = i >> 6, c = i & 63;
        SX[r*LD+c] = SV[r*LD+c] * sqrtf(sl[c]);
    }
    __syncthreads();
    mm64<true>(SX, SV, g_bm_sq + dom*MATSZ, 64);
    __syncthreads();
    for (int i = tid; i < MATSZ; i += 256) {
        int r = i >> 6, c = i & 63;
        SX[r*LD+c] = SV[r*LD+c] / sqrtf(sl[c]);
    }
    __syncthreads();
    mm64<true>(SX, SV, g_bm_isq + dom*MATSZ, 64);
}

// per-element: eig of M3 = bm_isq X bm_isq (register one-sided); XT -> g_XT, V3 -> g_V3.
__global__ void __launch_bounds__(256) k3_kernel(const float* __restrict__ X,
                                                 const int* __restrict__ dd) {
    extern __shared__ float sm[];
    float* S0 = sm; float* S1 = sm + BUF; float* S2 = sm + 2*BUF;
    __shared__ float lam[64], sl[64];
    const int n = blockIdx.x, tid = threadIdx.x;
    const int dom = dd[n];
    g2s(X + (size_t)n * MATSZ, S0);
    g2s(g_bm_isq + dom * MATSZ, S1);
    __syncthreads();
    mm64<false>(S1, S0, S2, LD);  __syncthreads();   // T = Q·X
    mm64<false>(S2, S1, S0, LD);  __syncthreads();   // M = T·Q -> S0
    symmetrize(S0, S1);           __syncthreads();   // A -> S1
    jacobi_os_reg(S1, lam);                          // S1 := V3 (orthonormal cols)
    if (tid < 64) sl[tid] = logf(fmaxf(lam[tid], EIG_EPS));
    __syncthreads();
    float lv = (tid < 64) ? sl[tid] : 0.0f;
    float sq = blockReduceSum(lv * lv);
    if (tid == 0) atomicAdd(&g_sumsq[dom], sq);
    for (int i = tid; i < MATSZ; i += 256) {
        int r = i >> 6, c = i & 63;
        S0[r*LD+c] = S1[r*LD+c] * sl[c];             // W = V3·diag(logλ)
    }
    __syncthreads();
    s2g(S1, g_V3 + (size_t)n * MATSZ);
    mm64<true>(S0, S1, g_XT + (size_t)n * MATSZ, 64);  // XT = W·V3^T
}

__global__ void __launch_bounds__(256) k3b_kernel(const int* __restrict__ dd) {
    __shared__ int sdom[128];
    const int e  = blockIdx.x * 256 + threadIdx.x;
    const int n0 = blockIdx.y * 128;
    if (threadIdx.x < 128) sdom[threadIdx.x] = dd[n0 + threadIdx.x];
    __syncthreads();
    float acc[NDOMS];
    #pragma unroll
    for (int k = 0; k < NDOMS; k++) acc[k] = 0.0f;
    for (int m = 0; m < 128; m++) {
        float x = g_XT[(size_t)(n0 + m) * MATSZ + e];
        int dom = sdom[m];
        #pragma unroll
        for (int k = 0; k < NDOMS; k++) acc[k] += (dom == k) ? x : 0.0f;
    }
    #pragma unroll
    for (int k = 0; k < NDOMS; k++) atomicAdd(&g_GT[k*MATSZ + e], acc[k]);
}

// per-domain (ETA=1 exact): rm = bm_sq expm(GT) bm_sq; GT2 = GT; var = sumsq/cnt - ||GT||^2.
__global__ void __launch_bounds__(256) k4_kernel(const float* __restrict__ mean,
                                                 const float* __restrict__ stdv) {
    extern __shared__ float sm[];
    float* SA = sm;           float* SV = sm + BUF;
    float* SQ = sm + 2*BUF;   float* SX = sm + 3*BUF;
    float* SG = sm + 4*BUF;
    __shared__ float sl[64];
    const int tid = threadIdx.x, b = blockIdx.x;

    if (b == NDOMS) {
        float dev = 0.0f;
        for (int i = tid; i < MATSZ; i += 256) {
            int r = i >> 6, c = i & 63;
            float mv = mean[i];
            SX[r*LD+c] = mv;
            dev += fabsf(mv - ((r == c) ? 1.0f : 0.0f));
        }
        float devT = blockReduceSum(dev);
        if (tid == 0) g_noBsq = (devT < 1e-6f) ? 1 : 0;
        __syncthreads();
        symmetrize(SX, SA); __syncthreads();
        jacobi_eig<true>(SA, SV, 1e-8f);
        if (tid < 64) sl[tid] = sqrtf(fmaxf(SA[tid*LD+tid], EIG_EPS));
        __syncthreads();
        for (int i = tid; i < MATSZ; i += 256) { int r=i>>6,c=i&63; SX[r*LD+c] = SV[r*LD+c]*sl[c]; }
        __syncthreads();
        mm64<true>(SX, SV, g_Bsq, 64);
        return;
    }
    const int dom = b;
    const float cntf = g_cnt[dom];
    float gn = 0.0f;
    for (int i = tid; i < MATSZ; i += 256) {
        int r = i >> 6, c = i & 63;
        float g = g_GT[dom*MATSZ+i] / cntf;
        SG[r*LD+c] = g;
        gn += g * g;
    }
    float gnorm2 = blockReduceSum(gn);
    __syncthreads();
    symmetrize(SG, SA); __syncthreads();
    jacobi_eig<true>(SA, SV, 1e-8f);        // eig(GT), indefinite
    if (tid < 64) sl[tid] = expf(SA[tid*LD+tid]);
    __syncthreads();
    for (int i = tid; i < MATSZ; i += 256) { int r=i>>6,c=i&63; SX[r*LD+c] = SV[r*LD+c]*sl[c]; }
    __syncthreads();
    mm64<true>(SX, SV, SQ, LD); __syncthreads();      // E = expm(GT)
    for (int i = tid; i < MATSZ; i += 256) { int r=i>>6,c=i&63; SA[r*LD+c] = g_bm_sq[dom*MATSZ+i]; }
    __syncthreads();
    mm64<false>(SA, SQ, SX, LD); __syncthreads();     // bm_sq·E
    mm64<false>(SX, SA, SV, LD); __syncthreads();     // rm
    symmetrize(SV, SA); __syncthreads();
    jacobi_eig<true>(SA, SQ, 1e-8f);                  // eig(rm)
    if (tid < 64) sl[tid] = fmaxf(SA[tid*LD+tid], EIG_EPS);
    __syncthreads();
    for (int i = tid; i < MATSZ; i += 256) { int r=i>>6,c=i&63; SX[r*LD+c] = SQ[r*LD+c]*rsqrtf(sl[c]); }
    __syncthreads();
    mm64<true>(SX, SQ, g_rm_isq + dom*MATSZ, 64);
    if (tid == 0) {
        float var = g_sumsq[dom] / cntf - gnorm2;
        g_s[dom]  = stdv[0] / sqrtf(var + EPS_C);
    }
}

// per-element normalize, warm-started: A' = V3^T M5 V3 (near-diagonal, SPD).
__global__ void __launch_bounds__(256) k5_kernel(const float* __restrict__ X,
                                                 const int* __restrict__ dd,
                                                 float* __restrict__ out) {
    extern __shared__ float sm[];
    float* S0 = sm; float* S1 = sm + BUF; float* S2 = sm + 2*BUF;
    __shared__ float lam[64], ff[64];
    const int n = blockIdx.x, tid = threadIdx.x;
    const int dom = dd[n];
    const int noB = g_noBsq;
    g2s(X + (size_t)n * MATSZ, S0);
    g2s(g_rm_isq + dom * MATSZ, S1);
    __syncthreads();
    mm64<false>(S1, S0, S2, LD);  __syncthreads();   // T = Q5·X
    mm64<false>(S2, S1, S0, LD);  __syncthreads();   // M5 -> S0
    g2s(g_V3 + (size_t)n * MATSZ, S1);               // V3 -> S1
    __syncthreads();
    mm64<false>(S0, S1, S2, LD);  __syncthreads();   // M5·V3 -> S2
    mm64_tA(S1, S2, S0);          __syncthreads();   // A' = V3^T·(M5·V3) -> S0
    symmetrize(S0, S2);           __syncthreads();   // A -> S2
    jacobi_os_reg(S2, lam);                          // S2 := V' (orthonormal)
    const float sgl = g_s[dom];
    if (tid < 64) ff[tid] = expf(sgl * logf(fmaxf(lam[tid], EIG_EPS)));
    __syncthreads();
    mm64<false>(S1, S2, S0, LD);  __syncthreads();   // G = V3·V' -> S0
    for (int i = tid; i < MATSZ; i += 256) {
        int r = i >> 6, c = i & 63;
        S1[r*LD+c] = S0[r*LD+c] * ff[c];             // W2 = G·diag(λ^s)
    }
    __syncthreads();
    if (noB) {
        mm64<true>(S1, S0, out + (size_t)n * MATSZ, 64);    // Xn = W2·G^T
    } else {
        mm64<true>(S1, S0, S2, LD);   __syncthreads();      // P -> S2
        g2s(g_Bsq, S0);               __syncthreads();
        mm64<false>(S0, S2, S1, LD);  __syncthreads();      // Bsq·P
        mm64<false>(S1, S0, out + (size_t)n * MATSZ, 64);   // Xn
    }
}

// ---------------- launch ----------------
extern "C" void kernel_launch(void* const* d_in, const int* in_sizes, int n_in,
                              void* d_out, int out_size) {
    const float* X    = (const float*)d_in[0];
    const int*   dd   = (const int*)  d_in[1];
    const float* mean = (const float*)d_in[2];
    const float* stdv = (const float*)d_in[3];
    float* out = (float*)d_out;

    const int SM3 = 3 * BUF * (int)sizeof(float);
    const int SM5 = 5 * BUF * (int)sizeof(float);
    cudaFuncSetAttribute(k2_kernel, cudaFuncAttributeMaxDynamicSharedMemorySize, SM3);
    cudaFuncSetAttribute(k3_kernel, cudaFuncAttributeMaxDynamicSharedMemorySize, SM3);
    cudaFuncSetAttribute(k4_kernel, cudaFuncAttributeMaxDynamicSharedMemorySize, SM5);
    cudaFuncSetAttribute(k5_kernel, cudaFuncAttributeMaxDynamicSharedMemorySize, SM3);

    kzero_kernel<<<128, 256>>>();
    k1_kernel<<<dim3(16, 32), 256>>>(X, dd);
    k2_kernel<<<NDOMS, 256, SM3>>>(dd);
    k3_kernel<<<NMAT, 256, SM3>>>(X, dd);
    k3b_kernel<<<dim3(16, 32), 256>>>(dd);
    k4_kernel<<<NDOMS + 1, 256, SM5>>>(mean, stdv);
    k5_kernel<<<NMAT, 256, SM3>>>(X, dd, out);
}

// round 12
// speedup vs baseline: 1.0017x; 1.0017x over previous
#include <cuda_runtime.h>
#include <math.h>

#define NDIM    64
#define LD      65
#define NMAT    4096
#define NDOMS   8
#define MATSZ   (NDIM*NDIM)
#define BUF     (NDIM*LD)
#define MAXSWEEPS 8
#define EIG_EPS 1e-4f
#define EPS_C   1e-5f

// ---------------- device scratch ----------------
__device__ float g_bmsum [NDOMS*MATSZ];
__device__ float g_bm_sq [NDOMS*MATSZ];
__device__ float g_bm_isq[NDOMS*MATSZ];
__device__ float g_GT    [NDOMS*MATSZ];
__device__ float g_rm_isq[NDOMS*MATSZ];
__device__ float g_Bsq   [MATSZ];
__device__ float g_sumsq [NDOMS];
__device__ float g_cnt   [NDOMS];
__device__ float g_s     [NDOMS];
__device__ int   g_noBsq;
__device__ float g_XT [(size_t)NMAT*MATSZ];
__device__ float g_V3 [(size_t)NMAT*MATSZ];

// ---------------- helpers ----------------
__device__ __forceinline__ float blockReduceSum(float v) {
    __shared__ float red[8];
    const unsigned m = 0xffffffffu;
    #pragma unroll
    for (int o = 16; o; o >>= 1) v += __shfl_down_sync(m, v, o);
    if ((threadIdx.x & 31) == 0) red[threadIdx.x >> 5] = v;
    __syncthreads();
    if (threadIdx.x < 32) {
        float x = (threadIdx.x < 8) ? red[threadIdx.x] : 0.0f;
        #pragma unroll
        for (int o = 4; o; o >>= 1) x += __shfl_down_sync(m, x, o);
        if (threadIdx.x == 0) red[0] = x;
    }
    __syncthreads();
    float r = red[0];
    __syncthreads();
    return r;
}

__device__ __forceinline__ void g2s(const float* __restrict__ g, float* __restrict__ S) {
    const float4* g4 = (const float4*)g;
    for (int i = threadIdx.x; i < MATSZ/4; i += 256) {
        float4 v = g4[i];
        int r = i >> 4, c = (i & 15) << 2;
        float* d = S + r*LD + c;
        d[0]=v.x; d[1]=v.y; d[2]=v.z; d[3]=v.w;
    }
}
__device__ __forceinline__ void s2g(const float* __restrict__ S, float* __restrict__ g) {
    float4* g4 = (float4*)g;
    for (int i = threadIdx.x; i < MATSZ/4; i += 256) {
        int r = i >> 4, c = (i & 15) << 2;
        const float* s = S + r*LD + c;
        g4[i] = make_float4(s[0], s[1], s[2], s[3]);
    }
}

template<bool TRANSB>
__device__ __forceinline__ void mm64(const float* __restrict__ A,
                                     const float* __restrict__ B,
                                     float* __restrict__ C, int ldc) {
    const int tid = threadIdx.x;
    const int r0 = (tid >> 4) << 2;
    const int c0 = (tid & 15) << 2;
    float acc[4][4];
    #pragma unroll
    for (int i = 0; i < 4; i++)
        #pragma unroll
        for (int j = 0; j < 4; j++) acc[i][j] = 0.0f;
    #pragma unroll 4
    for (int k = 0; k < 64; k++) {
        float a0 = A[(r0+0)*LD + k];
        float a1 = A[(r0+1)*LD + k];
        float a2 = A[(r0+2)*LD + k];
        float a3 = A[(r0+3)*LD + k];
        float b0, b1, b2, b3;
        if (TRANSB) {
            b0 = B[(c0+0)*LD + k]; b1 = B[(c0+1)*LD + k];
            b2 = B[(c0+2)*LD + k]; b3 = B[(c0+3)*LD + k];
        } else {
            b0 = B[k*LD + c0+0]; b1 = B[k*LD + c0+1];
            b2 = B[k*LD + c0+2]; b3 = B[k*LD + c0+3];
        }
        acc[0][0] += a0*b0; acc[0][1] += a0*b1; acc[0][2] += a0*b2; acc[0][3] += a0*b3;
        acc[1][0] += a1*b0; acc[1][1] += a1*b1; acc[1][2] += a1*b2; acc[1][3] += a1*b3;
        acc[2][0] += a2*b0; acc[2][1] += a2*b1; acc[2][2] += a2*b2; acc[2][3] += a2*b3;
        acc[3][0] += a3*b0; acc[3][1] += a3*b1; acc[3][2] += a3*b2; acc[3][3] += a3*b3;
    }
    #pragma unroll
    for (int i = 0; i < 4; i++)
        #pragma unroll
        for (int j = 0; j < 4; j++)
            C[(size_t)(r0+i)*ldc + c0 + j] = acc[i][j];
}

// C = A^T * B (both smem, stride LD)
__device__ __forceinline__ void mm64_tA(const float* __restrict__ A,
                                        const float* __restrict__ B,
                                        float* __restrict__ C) {
    const int tid = threadIdx.x;
    const int r0 = (tid >> 4) << 2;
    const int c0 = (tid & 15) << 2;
    float acc[4][4];
    #pragma unroll
    for (int i = 0; i < 4; i++)
        #pragma unroll
        for (int j = 0; j < 4; j++) acc[i][j] = 0.0f;
    #pragma unroll 4
    for (int k = 0; k < 64; k++) {
        float a0 = A[k*LD + r0+0];
        float a1 = A[k*LD + r0+1];
        float a2 = A[k*LD + r0+2];
        float a3 = A[k*LD + r0+3];
        float b0 = B[k*LD + c0+0], b1 = B[k*LD + c0+1];
        float b2 = B[k*LD + c0+2], b3 = B[k*LD + c0+3];
        acc[0][0] += a0*b0; acc[0][1] += a0*b1; acc[0][2] += a0*b2; acc[0][3] += a0*b3;
        acc[1][0] += a1*b0; acc[1][1] += a1*b1; acc[1][2] += a1*b2; acc[1][3] += a1*b3;
        acc[2][0] += a2*b0; acc[2][1] += a2*b1; acc[2][2] += a2*b2; acc[2][3] += a2*b3;
        acc[3][0] += a3*b0; acc[3][1] += a3*b1; acc[3][2] += a3*b2; acc[3][3] += a3*b3;
    }
    #pragma unroll
    for (int i = 0; i < 4; i++)
        #pragma unroll
        for (int j = 0; j < 4; j++)
            C[(r0+i)*LD + c0 + j] = acc[i][j];
}

__device__ __forceinline__ void symmetrize(const float* __restrict__ S, float* __restrict__ D) {
    for (int i = threadIdx.x; i < MATSZ; i += 256) {
        int r = i >> 6, c = i & 63;
        D[r*LD+c] = 0.5f*(S[r*LD+c] + S[c*LD+r]);
    }
}

// ---- two-sided Jacobi (per-domain kernels; handles indefinite) ----
template<bool INITV>
__device__ void jacobi_eig(float* A, float* V, float tol) {
    const int tid  = threadIdx.x;
    const int warp = tid >> 5;
    const int lane = tid & 31;
    const unsigned FULL = 0xffffffffu;
    if (INITV) {
        for (int i = tid; i < MATSZ; i += 256) {
            int r = i >> 6, c = i & 63;
            V[r*LD+c] = (r == c) ? 1.0f : 0.0f;
        }
        __syncthreads();
    }
    for (int sw = 0; sw < MAXSWEEPS; sw++) {
        float offs = 0.0f, tots = 0.0f;
        for (int i = tid; i < MATSZ; i += 256) {
            int r = i >> 6, c = i & 63;
            float a = A[r*LD+c], a2 = a*a;
            tots += a2;
            if (r != c) offs += a2;
        }
        float offT = blockReduceSum(offs);
        float totT = blockReduceSum(tots);
        if (offT <= tol * totT + 1e-30f) break;

        for (int rd = 0; rd < 63; rd++) {
            const int x = (rd * 32) % 63;
            int myp = 0, myq = 0; float myc = 1.0f, mys = 0.0f;
            if (lane < 4) {
                const int slot = warp * 4 + lane;
                if (slot == 0) { myp = x; myq = 63; }
                else {
                    int a = x + slot; if (a >= 63) a -= 63;
                    int b = x - slot; if (b < 0)   b += 63;
                    myp = min(a, b); myq = max(a, b);
                }
                const float apq = A[myp*LD+myq];
                const float app = A[myp*LD+myp];
                const float aqq = A[myq*LD+myq];
                if (fabsf(apq) > 2e-7f * (fabsf(app) + fabsf(aqq))) {
                    const float tau = (aqq - app) / (2.0f * apq);
                    float t = 1.0f / (fabsf(tau) + sqrtf(1.0f + tau*tau));
                    if (tau < 0.0f) t = -t;
                    myc = rsqrtf(1.0f + t*t);
                    mys = t * myc;
                }
            }
            int pp[4], qq[4]; float cc[4], ssv[4];
            #pragma unroll
            for (int t = 0; t < 4; t++) {
                pp[t]  = __shfl_sync(FULL, myp, t);
                qq[t]  = __shfl_sync(FULL, myq, t);
                cc[t]  = __shfl_sync(FULL, myc, t);
                ssv[t] = __shfl_sync(FULL, mys, t);
            }
            #pragma unroll
            for (int t = 0; t < 4; t++) {
                const float c = cc[t], s = ssv[t];
                if (s != 0.0f) {
                    float* Ap = A + pp[t]*LD;
                    float* Aq = A + qq[t]*LD;
                    #pragma unroll
                    for (int kk = 0; kk < 2; kk++) {
                        const int k = lane + 32*kk;
                        const float ap = Ap[k], aq = Aq[k];
                        Ap[k] = c*ap - s*aq;
                        Aq[k] = s*ap + c*aq;
                    }
                }
            }
            __syncthreads();
            float* Ar0 = A + lane*LD;
            float* Vr0 = V + lane*LD;
            #pragma unroll
            for (int t = 0; t < 4; t++) {
                const float c = cc[t], s = ssv[t];
                if (s != 0.0f) {
                    const int p = pp[t], q = qq[t];
                    #pragma unroll
                    for (int kk = 0; kk < 2; kk++) {
                        float* Ar = Ar0 + 32*LD*kk;
                        float* Vr = Vr0 + 32*LD*kk;
                        const float ap = Ar[p], aq = Ar[q];
                        Ar[p] = c*ap - s*aq;
                        Ar[q] = s*ap + c*aq;
                        const float vp = Vr[p], vq = Vr[q];
                        Vr[p] = c*vp - s*vq;
                        Vr[q] = s*vp + c*vq;
                    }
                }
            }
            __syncthreads();
        }
    }
}

// ---- register-resident one-sided Jacobi (SPD), Brent-Luk odd-even ordering ----
// Bm (smem, stride LD): SPD matrix in; on exit Bm columns = ORTHONORMAL eigenvectors
// (arbitrary order/sign), lam[j] = eigenvalue of column j.
// 32 workers x 8 threads; each worker holds 2 columns in registers.
// A-rounds: intra-worker (register-only). B-rounds: neighbor exchange via shfl
// (warp-internal) or a tiny smem staging buffer (7 warp boundaries).
__device__ void jacobi_os_reg(float* Bm, float* lam) {
    __shared__ float xb[7*64];
    __shared__ float xbn[8];
    __shared__ int chg;
    const int tid = threadIdx.x;
    const int w   = tid >> 3;        // worker 0..31
    const int g   = tid & 7;
    const int ww  = w & 3;           // worker within warp
    const int wp  = w >> 2;          // warp id
    const unsigned FULL = 0xffffffffu;
    float P[8], Q[8], R[8], xs[8];
    #pragma unroll
    for (int i = 0; i < 8; i++) {
        int k = g + 8*i;
        P[i] = Bm[k*LD + 2*w];
        Q[i] = Bm[k*LD + 2*w + 1];
    }
    if (tid == 0) chg = 0;
    __syncthreads();
    for (int sw = 0; sw < MAXSWEEPS; sw++) {
        // fresh carried norms each sweep
        float nP = 0.0f, nQ = 0.0f;
        #pragma unroll
        for (int i = 0; i < 8; i++) { nP += P[i]*P[i]; nQ += Q[i]*Q[i]; }
        #pragma unroll
        for (int o = 4; o; o >>= 1) { nP += __shfl_xor_sync(FULL, nP, o); nQ += __shfl_xor_sync(FULL, nQ, o); }
        for (int half = 0; half < 32; half++) {
            // ---------- A round: pair (2w, 2w+1), register-only ----------
            float d = 0.0f;
            #pragma unroll
            for (int i = 0; i < 8; i++) d += P[i]*Q[i];
            #pragma unroll
            for (int o = 4; o; o >>= 1) d += __shfl_xor_sync(FULL, d, o);
            if (d*d > 4e-14f * nP * nQ) {
                float tau = (nQ - nP) / (2.0f * d);
                float t = 1.0f / (fabsf(tau) + sqrtf(1.0f + tau*tau));
                if (tau < 0.0f) t = -t;
                float c = rsqrtf(1.0f + t*t), s = t*c;
                #pragma unroll
                for (int i = 0; i < 8; i++) {
                    float x = P[i], y = Q[i];
                    P[i] = s*x + c*y;        // y' -> pos 2w   (swap)
                    Q[i] = c*x - s*y;        // x' -> pos 2w+1
                }
                float tcs = 2.0f*c*s*d;
                float nPn = s*s*nP + tcs + c*c*nQ;
                float nQn = c*c*nP - tcs + s*s*nQ;
                nP = nPn; nQ = nQn;
                if (g == 0) chg = 1;
            } else {
                #pragma unroll
                for (int i = 0; i < 8; i++) { float x = P[i]; P[i] = Q[i]; Q[i] = x; }
                float x = nP; nP = nQ; nQ = x;
            }
            // ---------- B round: pair (2w+1, 2w+2) ----------
            // stage 1: obtain R = P of worker w+1
            if (ww == 0 && wp > 0) {
                #pragma unroll
                for (int i = 0; i < 8; i++) xb[(wp-1)*64 + g + 8*i] = P[i];
                if (g == 0) xbn[wp-1] = nP;
            }
            __syncthreads();
            float nR;
            #pragma unroll
            for (int i = 0; i < 8; i++) R[i] = __shfl_down_sync(FULL, P[i], 8);
            nR = __shfl_down_sync(FULL, nP, 8);
            if (ww == 3 && wp < 7) {
                #pragma unroll
                for (int i = 0; i < 8; i++) R[i] = xb[wp*64 + g + 8*i];
                nR = xbn[wp];
            }
            const bool doPair = (w <= 30);
            float d2 = 0.0f;
            #pragma unroll
            for (int i = 0; i < 8; i++) d2 += Q[i]*R[i];
            #pragma unroll
            for (int o = 4; o; o >>= 1) d2 += __shfl_xor_sync(FULL, d2, o);
            float nXs;
            if (doPair && d2*d2 > 4e-14f * nQ * nR) {
                float tau = (nR - nQ) / (2.0f * d2);
                float t = 1.0f / (fabsf(tau) + sqrtf(1.0f + tau*tau));
                if (tau < 0.0f) t = -t;
                float c = rsqrtf(1.0f + t*t), s = t*c;
                #pragma unroll
                for (int i = 0; i < 8; i++) {
                    float x = Q[i], y = R[i];
                    xs[i] = c*x - s*y;       // x' -> pos 2w+2 (send to w+1)
                    Q[i]  = s*x + c*y;       // y' -> pos 2w+1
                }
                float tcs = 2.0f*c*s*d2;
                nXs = c*c*nQ - tcs + s*s*nR;
                nQ  = s*s*nQ + tcs + c*c*nR;
                if (g == 0) chg = 1;
            } else {
                #pragma unroll
                for (int i = 0; i < 8; i++) xs[i] = Q[i];
                nXs = nQ;
                if (doPair) {
                    #pragma unroll
                    for (int i = 0; i < 8; i++) Q[i] = R[i];
                    nQ = nR;
                }
            }
            // stage 2: send xs -> worker w+1's new P
            if (ww == 3 && wp < 7) {
                #pragma unroll
                for (int i = 0; i < 8; i++) xb[wp*64 + g + 8*i] = xs[i];
                if (g == 0) xbn[wp] = nXs;
            }
            __syncthreads();
            #pragma unroll
            for (int i = 0; i < 8; i++) R[i] = __shfl_up_sync(FULL, xs[i], 8);
            nR = __shfl_up_sync(FULL, nXs, 8);
            if (ww == 0 && wp > 0) {
                #pragma unroll
                for (int i = 0; i < 8; i++) R[i] = xb[(wp-1)*64 + g + 8*i];
                nR = xbn[wp-1];
            }
            if (w >= 1) {
                #pragma unroll
                for (int i = 0; i < 8; i++) P[i] = R[i];
                nP = nR;
            }
        }
        int c = chg;
        __syncthreads();
        if (c == 0) break;
        if (tid == 0) chg = 0;
        __syncthreads();
    }
    // normalized eigenvector columns + eigenvalues (fresh norms)
    float a = 0.0f, b = 0.0f;
    #pragma unroll
    for (int i = 0; i < 8; i++) { a += P[i]*P[i]; b += Q[i]*Q[i]; }
    #pragma unroll
    for (int o = 4; o; o >>= 1) { a += __shfl_xor_sync(FULL, a, o); b += __shfl_xor_sync(FULL, b, o); }
    float la = sqrtf(a), lb = sqrtf(b);
    float ia = 1.0f / fmaxf(la, 1e-20f), ib = 1.0f / fmaxf(lb, 1e-20f);
    #pragma unroll
    for (int i = 0; i < 8; i++) {
        int k = g + 8*i;
        Bm[k*LD + 2*w]     = P[i]*ia;
        Bm[k*LD + 2*w + 1] = Q[i]*ib;
    }
    if (g == 0) { lam[2*w] = la; lam[2*w+1] = lb; }
    __syncthreads();
}

// ---------------- kernels ----------------
__global__ void kzero_kernel() {
    int i = blockIdx.x * blockDim.x + threadIdx.x;
    int stride = gridDim.x * blockDim.x;
    for (int j = i; j < NDOMS*MATSZ; j += stride) { g_bmsum[j] = 0.0f; g_GT[j] = 0.0f; }
    if (i < NDOMS) g_sumsq[i] = 0.0f;
}

__global__ void __launch_bounds__(256) k1_kernel(const float* __restrict__ X,
                                                 const int* __restrict__ dd) {
    __shared__ int sdom[128];
    const int e  = blockIdx.x * 256 + threadIdx.x;
    const int n0 = blockIdx.y * 128;
    if (threadIdx.x < 128) sdom[threadIdx.x] = dd[n0 + threadIdx.x];
    __syncthreads();
    float acc[NDOMS];
    #pragma unroll
    for (int k = 0; k < NDOMS; k++) acc[k] = 0.0f;
    for (int m = 0; m < 128; m++) {
        float x = X[(size_t)(n0 + m) * MATSZ + e];
        int dom = sdom[m];
        #pragma unroll
        for (int k = 0; k < NDOMS; k++) acc[k] += (dom == k) ? x : 0.0f;
    }
    #pragma unroll
    for (int k = 0; k < NDOMS; k++) atomicAdd(&g_bmsum[k*MATSZ + e], acc[k]);
}

__global__ void __launch_bounds__(256) k2_kernel(const int* __restrict__ dd) {
    extern __shared__ float sm[];
    float* SX = sm; float* SA = sm + BUF; float* SV = sm + 2*BUF;
    __shared__ float sl[64];
    const int dom = blockIdx.x, tid = threadIdx.x;

    float loc = 0.0f;
    for (int i = tid; i < NMAT; i += 256) loc += (dd[i] == dom) ? 1.0f : 0.0f;
    float cnt  = blockReduceSum(loc);
    float cntf = fmaxf(cnt, 1.0f);
    if (tid == 0) g_cnt[dom] = cntf;

    for (int i = tid; i < MATSZ; i += 256) {
        int r = i >> 6, c = i & 63;
        SX[r*LD+c] = g_bmsum[dom*MATSZ + i] / cntf;
    }
    __syncthreads();
    symmetrize(SX, SA);
    __syncthreads();
    jacobi_eig<true>(SA, SV, 1e-8f);
    if (tid < 64) sl[tid] = fmaxf(SA[tid*LD+tid], EIG_EPS);
    __syncthreads();
    for (int i = tid; i < MATSZ; i += 256) {
        int r = i >> 6, c = i & 63;
        SX[r*LD+c] = SV[r*LD+c] * sqrtf(sl[c]);
    }
    __syncthreads();
    mm64<true>(SX, SV, g_bm_sq + dom*MATSZ, 64);
    __syncthreads();
    for (int i = tid; i < MATSZ; i += 256) {
        int r = i >> 6, c = i & 63;
        SX[r*LD+c] = SV[r*LD+c] / sqrtf(sl[c]);
    }
    __syncthreads();
    mm64<true>(SX, SV, g_bm_isq + dom*MATSZ, 64);
}

// per-element: eig of M3 = bm_isq X bm_isq (register one-sided); XT -> g_XT, V3 -> g_V3.
__global__ void __launch_bounds__(256) k3_kernel(const float* __restrict__ X,
                                                 const int* __restrict__ dd) {
    extern __shared__ float sm[];
    float* S0 = sm; float* S1 = sm + BUF; float* S2 = sm + 2*BUF;
    __shared__ float lam[64], sl[64];
    const int n = blockIdx.x, tid = threadIdx.x;
    const int dom = dd[n];
    g2s(X + (size_t)n * MATSZ, S0);
    g2s(g_bm_isq + dom * MATSZ, S1);
    __syncthreads();
    mm64<false>(S1, S0, S2, LD);  __syncthreads();   // T = Q·X
    mm64<false>(S2, S1, S0, LD);  __syncthreads();   // M = T·Q -> S0
    symmetrize(S0, S1);           __syncthreads();   // A -> S1
    jacobi_os_reg(S1, lam);                          // S1 := V3 (orthonormal cols)
    if (tid < 64) sl[tid] = logf(fmaxf(lam[tid], EIG_EPS));
    __syncthreads();
    float lv = (tid < 64) ? sl[tid] : 0.0f;
    float sq = blockReduceSum(lv * lv);
    if (tid == 0) atomicAdd(&g_sumsq[dom], sq);
    for (int i = tid; i < MATSZ; i += 256) {
        int r = i >> 6, c = i & 63;
        S0[r*LD+c] = S1[r*LD+c] * sl[c];             // W = V3·diag(logλ)
    }
    __syncthreads();
    s2g(S1, g_V3 + (size_t)n * MATSZ);
    mm64<true>(S0, S1, g_XT + (size_t)n * MATSZ, 64);  // XT = W·V3^T
}

__global__ void __launch_bounds__(256) k3b_kernel(const int* __restrict__ dd) {
    __shared__ int sdom[128];
    const int e  = blockIdx.x * 256 + threadIdx.x;
    const int n0 = blockIdx.y * 128;
    if (threadIdx.x < 128) sdom[threadIdx.x] = dd[n0 + threadIdx.x];
    __syncthreads();
    float acc[NDOMS];
    #pragma unroll
    for (int k = 0; k < NDOMS; k++) acc[k] = 0.0f;
    for (int m = 0; m < 128; m++) {
        float x = g_XT[(size_t)(n0 + m) * MATSZ + e];
        int dom = sdom[m];
        #pragma unroll
        for (int k = 0; k < NDOMS; k++) acc[k] += (dom == k) ? x : 0.0f;
    }
    #pragma unroll
    for (int k = 0; k < NDOMS; k++) atomicAdd(&g_GT[k*MATSZ + e], acc[k]);
}

// per-domain (ETA=1 exact): rm = bm_sq expm(GT) bm_sq; GT2 = GT; var = sumsq/cnt - ||GT||^2.
__global__ void __launch_bounds__(256) k4_kernel(const float* __restrict__ mean,
                                                 const float* __restrict__ stdv) {
    extern __shared__ float sm[];
    float* SA = sm;           float* SV = sm + BUF;
    float* SQ = sm + 2*BUF;   float* SX = sm + 3*BUF;
    float* SG = sm + 4*BUF;
    __shared__ float sl[64];
    const int tid = threadIdx.x, b = blockIdx.x;

    if (b == NDOMS) {
        float dev = 0.0f;
        for (int i = tid; i < MATSZ; i += 256) {
            int r = i >> 6, c = i & 63;
            float mv = mean[i];
            SX[r*LD+c] = mv;
            dev += fabsf(mv - ((r == c) ? 1.0f : 0.0f));
        }
        float devT = blockReduceSum(dev);
        if (tid == 0) g_noBsq = (devT < 1e-6f) ? 1 : 0;
        __syncthreads();
        symmetrize(SX, SA); __syncthreads();
        jacobi_eig<true>(SA, SV, 1e-8f);
        if (tid < 64) sl[tid] = sqrtf(fmaxf(SA[tid*LD+tid], EIG_EPS));
        __syncthreads();
        for (int i = tid; i < MATSZ; i += 256) { int r=i>>6,c=i&63; SX[r*LD+c] = SV[r*LD+c]*sl[c]; }
        __syncthreads();
        mm64<true>(SX, SV, g_Bsq, 64);
        return;
    }
    const int dom = b;
    const float cntf = g_cnt[dom];
    float gn = 0.0f;
    for (int i = tid; i < MATSZ; i += 256) {
        int r = i >> 6, c = i & 63;
        float g = g_GT[dom*MATSZ+i] / cntf;
        SG[r*LD+c] = g;
        gn += g * g;
    }
    float gnorm2 = blockReduceSum(gn);
    __syncthreads();
    symmetrize(SG, SA); __syncthreads();
    jacobi_eig<true>(SA, SV, 1e-8f);        // eig(GT), indefinite
    if (tid < 64) sl[tid] = expf(SA[tid*LD+tid]);
    __syncthreads();
    for (int i = tid; i < MATSZ; i += 256) { int r=i>>6,c=i&63; SX[r*LD+c] = SV[r*LD+c]*sl[c]; }
    __syncthreads();
    mm64<true>(SX, SV, SQ, LD); __syncthreads();      // E = expm(GT)
    for (int i = tid; i < MATSZ; i += 256) { int r=i>>6,c=i&63; SA[r*LD+c] = g_bm_sq[dom*MATSZ+i]; }
    __syncthreads();
    mm64<false>(SA, SQ, SX, LD); __syncthreads();     // bm_sq·E
    mm64<false>(SX, SA, SV, LD); __syncthreads();     // rm
    symmetrize(SV, SA); __syncthreads();
    jacobi_eig<true>(SA, SQ, 1e-8f);                  // eig(rm)
    if (tid < 64) sl[tid] = fmaxf(SA[tid*LD+tid], EIG_EPS);
    __syncthreads();
    for (int i = tid; i < MATSZ; i += 256) { int r=i>>6,c=i&63; SX[r*LD+c] = SQ[r*LD+c]*rsqrtf(sl[c]); }
    __syncthreads();
    mm64<true>(SX, SQ, g_rm_isq + dom*MATSZ, 64);
    if (tid == 0) {
        float var = g_sumsq[dom] / cntf - gnorm2;
        g_s[dom]  = stdv[0] / sqrtf(var + EPS_C);
    }
}

// per-element normalize, warm-started: A' = V3^T M5 V3 (near-diagonal, SPD).
__global__ void __launch_bounds__(256) k5_kernel(const float* __restrict__ X,
                                                 const int* __restrict__ dd,
                                                 float* __restrict__ out) {
    extern __shared__ float sm[];
    float* S0 = sm; float* S1 = sm + BUF; float* S2 = sm + 2*BUF;
    __shared__ float lam[64], ff[64];
    const int n = blockIdx.x, tid = threadIdx.x;
    const int dom = dd[n];
    const int noB = g_noBsq;
    g2s(X + (size_t)n * MATSZ, S0);
    g2s(g_rm_isq + dom * MATSZ, S1);
    __syncthreads();
    mm64<false>(S1, S0, S2, LD);  __syncthreads();   // T = Q5·X
    mm64<false>(S2, S1, S0, LD);  __syncthreads();   // M5 -> S0
    g2s(g_V3 + (size_t)n * MATSZ, S1);               // V3 -> S1
    __syncthreads();
    mm64<false>(S0, S1, S2, LD);  __syncthreads();   // M5·V3 -> S2
    mm64_tA(S1, S2, S0);          __syncthreads();   // A' = V3^T·(M5·V3) -> S0
    symmetrize(S0, S2);           __syncthreads();   // A -> S2
    jacobi_os_reg(S2, lam);                          // S2 := V' (orthonormal)
    const float sgl = g_s[dom];
    if (tid < 64) ff[tid] = expf(sgl * logf(fmaxf(lam[tid], EIG_EPS)));
    __syncthreads();
    mm64<false>(S1, S2, S0, LD);  __syncthreads();   // G = V3·V' -> S0
    for (int i = tid; i < MATSZ; i += 256) {
        int r = i >> 6, c = i & 63;
        S1[r*LD+c] = S0[r*LD+c] * ff[c];             // W2 = G·diag(λ^s)
    }
    __syncthreads();
    if (noB) {
        mm64<true>(S1, S0, out + (size_t)n * MATSZ, 64);    // Xn = W2·G^T
    } else {
        mm64<true>(S1, S0, S2, LD);   __syncthreads();      // P -> S2
        g2s(g_Bsq, S0);               __syncthreads();
        mm64<false>(S0, S2, S1, LD);  __syncthreads();      // Bsq·P
        mm64<false>(S1, S0, out + (size_t)n * MATSZ, 64);   // Xn
    }
}

// ---------------- launch ----------------
extern "C" void kernel_launch(void* const* d_in, const int* in_sizes, int n_in,
                              void* d_out, int out_size) {
    const float* X    = (const float*)d_in[0];
    const int*   dd   = (const int*)  d_in[1];
    const float* mean = (const float*)d_in[2];
    const float* stdv = (const float*)d_in[3];
    float* out = (float*)d_out;

    const int SM3 = 3 * BUF * (int)sizeof(float);
    const int SM5 = 5 * BUF * (int)sizeof(float);
    cudaFuncSetAttribute(k2_kernel, cudaFuncAttributeMaxDynamicSharedMemorySize, SM3);
    cudaFuncSetAttribute(k3_kernel, cudaFuncAttributeMaxDynamicSharedMemorySize, SM3);
    cudaFuncSetAttribute(k4_kernel, cudaFuncAttributeMaxDynamicSharedMemorySize, SM5);
    cudaFuncSetAttribute(k5_kernel, cudaFuncAttributeMaxDynamicSharedMemorySize, SM3);

    kzero_kernel<<<128, 256>>>();
    k1_kernel<<<dim3(16, 32), 256>>>(X, dd);
    k2_kernel<<<NDOMS, 256, SM3>>>(dd);
    k3_kernel<<<NMAT, 256, SM3>>>(X, dd);
    k3b_kernel<<<dim3(16, 32), 256>>>(dd);
    k4_kernel<<<NDOMS + 1, 256, SM5>>>(mean, stdv);
    k5_kernel<<<NMAT, 256, SM3>>>(X, dd, out);
}

// round 13
// speedup vs baseline: 1.0027x; 1.0009x over previous
#include <cuda_runtime.h>
#include <math.h>

#define NDIM    64
#define LD      65
#define NMAT    4096
#define NDOMS   8
#define MATSZ   (NDIM*NDIM)
#define BUF     (NDIM*LD)
#define MAXSWEEPS 8
#define EIG_EPS 1e-4f
#define EPS_C   1e-5f

// ---------------- device scratch ----------------
__device__ float g_bmsum [NDOMS*MATSZ];
__device__ float g_bm_sq [NDOMS*MATSZ];
__device__ float g_bm_isq[NDOMS*MATSZ];
__device__ float g_GT    [NDOMS*MATSZ];
__device__ float g_rm_isq[NDOMS*MATSZ];
__device__ float g_Bsq   [MATSZ];
__device__ float g_sumsq [NDOMS];
__device__ float g_cnt   [NDOMS];
__device__ float g_s     [NDOMS];
__device__ int   g_noBsq;
__device__ float g_XT [(size_t)NMAT*MATSZ];
__device__ float g_V3 [(size_t)NMAT*MATSZ];

// ---------------- helpers ----------------
__device__ __forceinline__ float blockReduceSum(float v) {
    __shared__ float red[8];
    const unsigned m = 0xffffffffu;
    #pragma unroll
    for (int o = 16; o; o >>= 1) v += __shfl_down_sync(m, v, o);
    if ((threadIdx.x & 31) == 0) red[threadIdx.x >> 5] = v;
    __syncthreads();
    if (threadIdx.x < 32) {
        float x = (threadIdx.x < 8) ? red[threadIdx.x] : 0.0f;
        #pragma unroll
        for (int o = 4; o; o >>= 1) x += __shfl_down_sync(m, x, o);
        if (threadIdx.x == 0) red[0] = x;
    }
    __syncthreads();
    float r = red[0];
    __syncthreads();
    return r;
}

__device__ __forceinline__ void g2s(const float* __restrict__ g, float* __restrict__ S) {
    const float4* g4 = (const float4*)g;
    for (int i = threadIdx.x; i < MATSZ/4; i += 256) {
        float4 v = g4[i];
        int r = i >> 4, c = (i & 15) << 2;
        float* d = S + r*LD + c;
        d[0]=v.x; d[1]=v.y; d[2]=v.z; d[3]=v.w;
    }
}
__device__ __forceinline__ void s2g(const float* __restrict__ S, float* __restrict__ g) {
    float4* g4 = (float4*)g;
    for (int i = threadIdx.x; i < MATSZ/4; i += 256) {
        int r = i >> 4, c = (i & 15) << 2;
        const float* s = S + r*LD + c;
        g4[i] = make_float4(s[0], s[1], s[2], s[3]);
    }
}

template<bool TRANSB>
__device__ __forceinline__ void mm64(const float* __restrict__ A,
                                     const float* __restrict__ B,
                                     float* __restrict__ C, int ldc) {
    const int tid = threadIdx.x;
    const int r0 = (tid >> 4) << 2;
    const int c0 = (tid & 15) << 2;
    float acc[4][4];
    #pragma unroll
    for (int i = 0; i < 4; i++)
        #pragma unroll
        for (int j = 0; j < 4; j++) acc[i][j] = 0.0f;
    #pragma unroll 4
    for (int k = 0; k < 64; k++) {
        float a0 = A[(r0+0)*LD + k];
        float a1 = A[(r0+1)*LD + k];
        float a2 = A[(r0+2)*LD + k];
        float a3 = A[(r0+3)*LD + k];
        float b0, b1, b2, b3;
        if (TRANSB) {
            b0 = B[(c0+0)*LD + k]; b1 = B[(c0+1)*LD + k];
            b2 = B[(c0+2)*LD + k]; b3 = B[(c0+3)*LD + k];
        } else {
            b0 = B[k*LD + c0+0]; b1 = B[k*LD + c0+1];
            b2 = B[k*LD + c0+2]; b3 = B[k*LD + c0+3];
        }
        acc[0][0] += a0*b0; acc[0][1] += a0*b1; acc[0][2] += a0*b2; acc[0][3] += a0*b3;
        acc[1][0] += a1*b0; acc[1][1] += a1*b1; acc[1][2] += a1*b2; acc[1][3] += a1*b3;
        acc[2][0] += a2*b0; acc[2][1] += a2*b1; acc[2][2] += a2*b2; acc[2][3] += a2*b3;
        acc[3][0] += a3*b0; acc[3][1] += a3*b1; acc[3][2] += a3*b2; acc[3][3] += a3*b3;
    }
    #pragma unroll
    for (int i = 0; i < 4; i++)
        #pragma unroll
        for (int j = 0; j < 4; j++)
            C[(size_t)(r0+i)*ldc + c0 + j] = acc[i][j];
}

// C = A^T * B (both smem, stride LD)
__device__ __forceinline__ void mm64_tA(const float* __restrict__ A,
                                        const float* __restrict__ B,
                                        float* __restrict__ C) {
    const int tid = threadIdx.x;
    const int r0 = (tid >> 4) << 2;
    const int c0 = (tid & 15) << 2;
    float acc[4][4];
    #pragma unroll
    for (int i = 0; i < 4; i++)
        #pragma unroll
        for (int j = 0; j < 4; j++) acc[i][j] = 0.0f;
    #pragma unroll 4
    for (int k = 0; k < 64; k++) {
        float a0 = A[k*LD + r0+0];
        float a1 = A[k*LD + r0+1];
        float a2 = A[k*LD + r0+2];
        float a3 = A[k*LD + r0+3];
        float b0 = B[k*LD + c0+0], b1 = B[k*LD + c0+1];
        float b2 = B[k*LD + c0+2], b3 = B[k*LD + c0+3];
        acc[0][0] += a0*b0; acc[0][1] += a0*b1; acc[0][2] += a0*b2; acc[0][3] += a0*b3;
        acc[1][0] += a1*b0; acc[1][1] += a1*b1; acc[1][2] += a1*b2; acc[1][3] += a1*b3;
        acc[2][0] += a2*b0; acc[2][1] += a2*b1; acc[2][2] += a2*b2; acc[2][3] += a2*b3;
        acc[3][0] += a3*b0; acc[3][1] += a3*b1; acc[3][2] += a3*b2; acc[3][3] += a3*b3;
    }
    #pragma unroll
    for (int i = 0; i < 4; i++)
        #pragma unroll
        for (int j = 0; j < 4; j++)
            C[(r0+i)*LD + c0 + j] = acc[i][j];
}

__device__ __forceinline__ void symmetrize(const float* __restrict__ S, float* __restrict__ D) {
    for (int i = threadIdx.x; i < MATSZ; i += 256) {
        int r = i >> 6, c = i & 63;
        D[r*LD+c] = 0.5f*(S[r*LD+c] + S[c*LD+r]);
    }
}

// ---- two-sided Jacobi (per-domain kernels; handles indefinite) ----
template<bool INITV>
__device__ void jacobi_eig(float* A, float* V, float tol) {
    const int tid  = threadIdx.x;
    const int warp = tid >> 5;
    const int lane = tid & 31;
    const unsigned FULL = 0xffffffffu;
    if (INITV) {
        for (int i = tid; i < MATSZ; i += 256) {
            int r = i >> 6, c = i & 63;
            V[r*LD+c] = (r == c) ? 1.0f : 0.0f;
        }
        __syncthreads();
    }
    for (int sw = 0; sw < MAXSWEEPS; sw++) {
        float offs = 0.0f, tots = 0.0f;
        for (int i = tid; i < MATSZ; i += 256) {
            int r = i >> 6, c = i & 63;
            float a = A[r*LD+c], a2 = a*a;
            tots += a2;
            if (r != c) offs += a2;
        }
        float offT = blockReduceSum(offs);
        float totT = blockReduceSum(tots);
        if (offT <= tol * totT + 1e-30f) break;

        for (int rd = 0; rd < 63; rd++) {
            const int x = (rd * 32) % 63;
            int myp = 0, myq = 0; float myc = 1.0f, mys = 0.0f;
            if (lane < 4) {
                const int slot = warp * 4 + lane;
                if (slot == 0) { myp = x; myq = 63; }
                else {
                    int a = x + slot; if (a >= 63) a -= 63;
                    int b = x - slot; if (b < 0)   b += 63;
                    myp = min(a, b); myq = max(a, b);
                }
                const float apq = A[myp*LD+myq];
                const float app = A[myp*LD+myp];
                const float aqq = A[myq*LD+myq];
                if (fabsf(apq) > 2e-7f * (fabsf(app) + fabsf(aqq))) {
                    const float tau = (aqq - app) / (2.0f * apq);
                    float t = 1.0f / (fabsf(tau) + sqrtf(1.0f + tau*tau));
                    if (tau < 0.0f) t = -t;
                    myc = rsqrtf(1.0f + t*t);
                    mys = t * myc;
                }
            }
            int pp[4], qq[4]; float cc[4], ssv[4];
            #pragma unroll
            for (int t = 0; t < 4; t++) {
                pp[t]  = __shfl_sync(FULL, myp, t);
                qq[t]  = __shfl_sync(FULL, myq, t);
                cc[t]  = __shfl_sync(FULL, myc, t);
                ssv[t] = __shfl_sync(FULL, mys, t);
            }
            #pragma unroll
            for (int t = 0; t < 4; t++) {
                const float c = cc[t], s = ssv[t];
                if (s != 0.0f) {
                    float* Ap = A + pp[t]*LD;
                    float* Aq = A + qq[t]*LD;
                    #pragma unroll
                    for (int kk = 0; kk < 2; kk++) {
                        const int k = lane + 32*kk;
                        const float ap = Ap[k], aq = Aq[k];
                        Ap[k] = c*ap - s*aq;
                        Aq[k] = s*ap + c*aq;
                    }
                }
            }
            __syncthreads();
            float* Ar0 = A + lane*LD;
            float* Vr0 = V + lane*LD;
            #pragma unroll
            for (int t = 0; t < 4; t++) {
                const float c = cc[t], s = ssv[t];
                if (s != 0.0f) {
                    const int p = pp[t], q = qq[t];
                    #pragma unroll
                    for (int kk = 0; kk < 2; kk++) {
                        float* Ar = Ar0 + 32*LD*kk;
                        float* Vr = Vr0 + 32*LD*kk;
                        const float ap = Ar[p], aq = Ar[q];
                        Ar[p] = c*ap - s*aq;
                        Ar[q] = s*ap + c*aq;
                        const float vp = Vr[p], vq = Vr[q];
                        Vr[p] = c*vp - s*vq;
                        Vr[q] = s*vp + c*vq;
                    }
                }
            }
            __syncthreads();
        }
    }
}

// ---- register-resident one-sided Jacobi (SPD), Brent-Luk odd-even ordering ----
// Bm (smem, stride LD): SPD matrix in; on exit Bm columns = ORTHONORMAL eigenvectors
// (arbitrary order/sign), lam[j] = eigenvalue of column j.
// 32 workers x 8 threads; each worker holds 2 columns in registers.
// A-rounds: intra-worker (register-only). B-rounds: neighbor exchange via shfl
// (warp-internal) or a tiny smem staging buffer (7 warp boundaries).
__device__ void jacobi_os_reg(float* Bm, float* lam) {
    __shared__ float xb[7*64];
    __shared__ float xbn[8];
    __shared__ int chg;
    const int tid = threadIdx.x;
    const int w   = tid >> 3;        // worker 0..31
    const int g   = tid & 7;
    const int ww  = w & 3;           // worker within warp
    const int wp  = w >> 2;          // warp id
    const unsigned FULL = 0xffffffffu;
    float P[8], Q[8], R[8], xs[8];
    #pragma unroll
    for (int i = 0; i < 8; i++) {
        int k = g + 8*i;
        P[i] = Bm[k*LD + 2*w];
        Q[i] = Bm[k*LD + 2*w + 1];
    }
    if (tid == 0) chg = 0;
    __syncthreads();
    for (int sw = 0; sw < MAXSWEEPS; sw++) {
        // fresh carried norms each sweep
        float nP = 0.0f, nQ = 0.0f;
        #pragma unroll
        for (int i = 0; i < 8; i++) { nP += P[i]*P[i]; nQ += Q[i]*Q[i]; }
        #pragma unroll
        for (int o = 4; o; o >>= 1) { nP += __shfl_xor_sync(FULL, nP, o); nQ += __shfl_xor_sync(FULL, nQ, o); }
        for (int half = 0; half < 32; half++) {
            // ---------- A round: pair (2w, 2w+1), register-only ----------
            float d = 0.0f;
            #pragma unroll
            for (int i = 0; i < 8; i++) d += P[i]*Q[i];
            #pragma unroll
            for (int o = 4; o; o >>= 1) d += __shfl_xor_sync(FULL, d, o);
            if (d*d > 4e-14f * nP * nQ) {
                float tau = (nQ - nP) / (2.0f * d);
                float t = 1.0f / (fabsf(tau) + sqrtf(1.0f + tau*tau));
                if (tau < 0.0f) t = -t;
                float c = rsqrtf(1.0f + t*t), s = t*c;
                #pragma unroll
                for (int i = 0; i < 8; i++) {
                    float x = P[i], y = Q[i];
                    P[i] = s*x + c*y;        // y' -> pos 2w   (swap)
                    Q[i] = c*x - s*y;        // x' -> pos 2w+1
                }
                float tcs = 2.0f*c*s*d;
                float nPn = s*s*nP + tcs + c*c*nQ;
                float nQn = c*c*nP - tcs + s*s*nQ;
                nP = nPn; nQ = nQn;
                if (g == 0) chg = 1;
            } else {
                #pragma unroll
                for (int i = 0; i < 8; i++) { float x = P[i]; P[i] = Q[i]; Q[i] = x; }
                float x = nP; nP = nQ; nQ = x;
            }
            // ---------- B round: pair (2w+1, 2w+2) ----------
            // stage 1: obtain R = P of worker w+1
            if (ww == 0 && wp > 0) {
                #pragma unroll
                for (int i = 0; i < 8; i++) xb[(wp-1)*64 + g + 8*i] = P[i];
                if (g == 0) xbn[wp-1] = nP;
            }
            __syncthreads();
            float nR;
            #pragma unroll
            for (int i = 0; i < 8; i++) R[i] = __shfl_down_sync(FULL, P[i], 8);
            nR = __shfl_down_sync(FULL, nP, 8);
            if (ww == 3 && wp < 7) {
                #pragma unroll
                for (int i = 0; i < 8; i++) R[i] = xb[wp*64 + g + 8*i];
                nR = xbn[wp];
            }
            const bool doPair = (w <= 30);
            float d2 = 0.0f;
            #pragma unroll
            for (int i = 0; i < 8; i++) d2 += Q[i]*R[i];
            #pragma unroll
            for (int o = 4; o; o >>= 1) d2 += __shfl_xor_sync(FULL, d2, o);
            float nXs;
            if (doPair && d2*d2 > 4e-14f * nQ * nR) {
                float tau = (nR - nQ) / (2.0f * d2);
                float t = 1.0f / (fabsf(tau) + sqrtf(1.0f + tau*tau));
                if (tau < 0.0f) t = -t;
                float c = rsqrtf(1.0f + t*t), s = t*c;
                #pragma unroll
                for (int i = 0; i < 8; i++) {
                    float x = Q[i], y = R[i];
                    xs[i] = c*x - s*y;       // x' -> pos 2w+2 (send to w+1)
                    Q[i]  = s*x + c*y;       // y' -> pos 2w+1
                }
                float tcs = 2.0f*c*s*d2;
                nXs = c*c*nQ - tcs + s*s*nR;
                nQ  = s*s*nQ + tcs + c*c*nR;
                if (g == 0) chg = 1;
            } else {
                #pragma unroll
                for (int i = 0; i < 8; i++) xs[i] = Q[i];
                nXs = nQ;
                if (doPair) {
                    #pragma unroll
                    for (int i = 0; i < 8; i++) Q[i] = R[i];
                    nQ = nR;
                }
            }
            // stage 2: send xs -> worker w+1's new P
            if (ww == 3 && wp < 7) {
                #pragma unroll
                for (int i = 0; i < 8; i++) xb[wp*64 + g + 8*i] = xs[i];
                if (g == 0) xbn[wp] = nXs;
            }
            __syncthreads();
            #pragma unroll
            for (int i = 0; i < 8; i++) R[i] = __shfl_up_sync(FULL, xs[i], 8);
            nR = __shfl_up_sync(FULL, nXs, 8);
            if (ww == 0 && wp > 0) {
                #pragma unroll
                for (int i = 0; i < 8; i++) R[i] = xb[(wp-1)*64 + g + 8*i];
                nR = xbn[wp-1];
            }
            if (w >= 1) {
                #pragma unroll
                for (int i = 0; i < 8; i++) P[i] = R[i];
                nP = nR;
            }
        }
        int c = chg;
        __syncthreads();
        if (c == 0) break;
        if (tid == 0) chg = 0;
        __syncthreads();
    }
    // normalized eigenvector columns + eigenvalues (fresh norms)
    float a = 0.0f, b = 0.0f;
    #pragma unroll
    for (int i = 0; i < 8; i++) { a += P[i]*P[i]; b += Q[i]*Q[i]; }
    #pragma unroll
    for (int o = 4; o; o >>= 1) { a += __shfl_xor_sync(FULL, a, o); b += __shfl_xor_sync(FULL, b, o); }
    float la = sqrtf(a), lb = sqrtf(b);
    float ia = 1.0f / fmaxf(la, 1e-20f), ib = 1.0f / fmaxf(lb, 1e-20f);
    #pragma unroll
    for (int i = 0; i < 8; i++) {
        int k = g + 8*i;
        Bm[k*LD + 2*w]     = P[i]*ia;
        Bm[k*LD + 2*w + 1] = Q[i]*ib;
    }
    if (g == 0) { lam[2*w] = la; lam[2*w+1] = lb; }
    __syncthreads();
}

// ---------------- kernels ----------------
__global__ void kzero_kernel() {
    int i = blockIdx.x * blockDim.x + threadIdx.x;
    int stride = gridDim.x * blockDim.x;
    for (int j = i; j < NDOMS*MATSZ; j += stride) { g_bmsum[j] = 0.0f; g_GT[j] = 0.0f; }
    if (i < NDOMS) g_sumsq[i] = 0.0f;
}

__global__ void __launch_bounds__(256) k1_kernel(const float* __restrict__ X,
                                                 const int* __restrict__ dd) {
    __shared__ int sdom[128];
    const int e  = blockIdx.x * 256 + threadIdx.x;
    const int n0 = blockIdx.y * 128;
    if (threadIdx.x < 128) sdom[threadIdx.x] = dd[n0 + threadIdx.x];
    __syncthreads();
    float acc[NDOMS];
    #pragma unroll
    for (int k = 0; k < NDOMS; k++) acc[k] = 0.0f;
    for (int m = 0; m < 128; m++) {
        float x = X[(size_t)(n0 + m) * MATSZ + e];
        int dom = sdom[m];
        #pragma unroll
        for (int k = 0; k < NDOMS; k++) acc[k] += (dom == k) ? x : 0.0f;
    }
    #pragma unroll
    for (int k = 0; k < NDOMS; k++) atomicAdd(&g_bmsum[k*MATSZ + e], acc[k]);
}

__global__ void __launch_bounds__(256) k2_kernel(const int* __restrict__ dd) {
    extern __shared__ float sm[];
    float* SX = sm; float* SA = sm + BUF; float* SV = sm + 2*BUF;
    __shared__ float sl[64];
    const int dom = blockIdx.x, tid = threadIdx.x;

    float loc = 0.0f;
    for (int i = tid; i < NMAT; i += 256) loc += (dd[i] == dom) ? 1.0f : 0.0f;
    float cnt  = blockReduceSum(loc);
    float cntf = fmaxf(cnt, 1.0f);
    if (tid == 0) g_cnt[dom] = cntf;

    for (int i = tid; i < MATSZ; i += 256) {
        int r = i >> 6, c = i & 63;
        SX[r*LD+c] = g_bmsum[dom*MATSZ + i] / cntf;
    }
    __syncthreads();
    symmetrize(SX, SA);
    __syncthreads();
    jacobi_eig<true>(SA, SV, 1e-8f);
    if (tid < 64) sl[tid] = fmaxf(SA[tid*LD+tid], EIG_EPS);
    __syncthreads();
    for (int i = tid; i < MATSZ; i += 256) {
        int r = i >> 6, c = i & 63;
        SX[r*LD+c] = SV[r*LD+c] * sqrtf(sl[c]);
    }
    __syncthreads();
    mm64<true>(SX, SV, g_bm_sq + dom*MATSZ, 64);
    __syncthreads();
    for (int i = tid; i < MATSZ; i += 256) {
        int r = i >> 6, c = i & 63;
        SX[r*LD+c] = SV[r*LD+c] / sqrtf(sl[c]);
    }
    __syncthreads();
    mm64<true>(SX, SV, g_bm_isq + dom*MATSZ, 64);
}

// per-element: eig of M3 = bm_isq X bm_isq (register one-sided); XT -> g_XT, V3 -> g_V3.
__global__ void __launch_bounds__(256) k3_kernel(const float* __restrict__ X,
                                                 const int* __restrict__ dd) {
    extern __shared__ float sm[];
    float* S0 = sm; float* S1 = sm + BUF; float* S2 = sm + 2*BUF;
    __shared__ float lam[64], sl[64];
    const int n = blockIdx.x, tid = threadIdx.x;
    const int dom = dd[n];
    g2s(X + (size_t)n * MATSZ, S0);
    g2s(g_bm_isq + dom * MATSZ, S1);
    __syncthreads();
    mm64<false>(S1, S0, S2, LD);  __syncthreads();   // T = Q·X
    mm64<false>(S2, S1, S0, LD);  __syncthreads();   // M = T·Q -> S0
    symmetrize(S0, S1);           __syncthreads();   // A -> S1
    jacobi_os_reg(S1, lam);                          // S1 := V3 (orthonormal cols)
    if (tid < 64) sl[tid] = logf(fmaxf(lam[tid], EIG_EPS));
    __syncthreads();
    float lv = (tid < 64) ? sl[tid] : 0.0f;
    float sq = blockReduceSum(lv * lv);
    if (tid == 0) atomicAdd(&g_sumsq[dom], sq);
    for (int i = tid; i < MATSZ; i += 256) {
        int r = i >> 6, c = i & 63;
        S0[r*LD+c] = S1[r*LD+c] * sl[c];             // W = V3·diag(logλ)
    }
    __syncthreads();
    s2g(S1, g_V3 + (size_t)n * MATSZ);
    mm64<true>(S0, S1, g_XT + (size_t)n * MATSZ, 64);  // XT = W·V3^T
}

__global__ void __launch_bounds__(256) k3b_kernel(const int* __restrict__ dd) {
    __shared__ int sdom[128];
    const int e  = blockIdx.x * 256 + threadIdx.x;
    const int n0 = blockIdx.y * 128;
    if (threadIdx.x < 128) sdom[threadIdx.x] = dd[n0 + threadIdx.x];
    __syncthreads();
    float acc[NDOMS];
    #pragma unroll
    for (int k = 0; k < NDOMS; k++) acc[k] = 0.0f;
    for (int m = 0; m < 128; m++) {
        float x = g_XT[(size_t)(n0 + m) * MATSZ + e];
        int dom = sdom[m];
        #pragma unroll
        for (int k = 0; k < NDOMS; k++) acc[k] += (dom == k) ? x : 0.0f;
    }
    #pragma unroll
    for (int k = 0; k < NDOMS; k++) atomicAdd(&g_GT[k*MATSZ + e], acc[k]);
}

// per-domain (ETA=1 exact): rm = bm_sq expm(GT) bm_sq; GT2 = GT; var = sumsq/cnt - ||GT||^2.
__global__ void __launch_bounds__(256) k4_kernel(const float* __restrict__ mean,
                                                 const float* __restrict__ stdv) {
    extern __shared__ float sm[];
    float* SA = sm;           float* SV = sm + BUF;
    float* SQ = sm + 2*BUF;   float* SX = sm + 3*BUF;
    float* SG = sm + 4*BUF;
    __shared__ float sl[64];
    const int tid = threadIdx.x, b = blockIdx.x;

    if (b == NDOMS) {
        float dev = 0.0f;
        for (int i = tid; i < MATSZ; i += 256) {
            int r = i >> 6, c = i & 63;
            float mv = mean[i];
            SX[r*LD+c] = mv;
            dev += fabsf(mv - ((r == c) ? 1.0f : 0.0f));
        }
        float devT = blockReduceSum(dev);
        if (tid == 0) g_noBsq = (devT < 1e-6f) ? 1 : 0;
        __syncthreads();
        symmetrize(SX, SA); __syncthreads();
        jacobi_eig<true>(SA, SV, 1e-8f);
        if (tid < 64) sl[tid] = sqrtf(fmaxf(SA[tid*LD+tid], EIG_EPS));
        __syncthreads();
        for (int i = tid; i < MATSZ; i += 256) { int r=i>>6,c=i&63; SX[r*LD+c] = SV[r*LD+c]*sl[c]; }
        __syncthreads();
        mm64<true>(SX, SV, g_Bsq, 64);
        return;
    }
    const int dom = b;
    const float cntf = g_cnt[dom];
    float gn = 0.0f;
    for (int i = tid; i < MATSZ; i += 256) {
        int r = i >> 6, c = i & 63;
        float g = g_GT[dom*MATSZ+i] / cntf;
        SG[r*LD+c] = g;
        gn += g * g;
    }
    float gnorm2 = blockReduceSum(gn);
    __syncthreads();
    symmetrize(SG, SA); __syncthreads();
    jacobi_eig<true>(SA, SV, 1e-8f);        // eig(GT), indefinite
    if (tid < 64) sl[tid] = expf(SA[tid*LD+tid]);
    __syncthreads();
    for (int i = tid; i < MATSZ; i += 256) { int r=i>>6,c=i&63; SX[r*LD+c] = SV[r*LD+c]*sl[c]; }
    __syncthreads();
    mm64<true>(SX, SV, SQ, LD); __syncthreads();      // E = expm(GT)
    for (int i = tid; i < MATSZ; i += 256) { int r=i>>6,c=i&63; SA[r*LD+c] = g_bm_sq[dom*MATSZ+i]; }
    __syncthreads();
    mm64<false>(SA, SQ, SX, LD); __syncthreads();     // bm_sq·E
    mm64<false>(SX, SA, SV, LD); __syncthreads();     // rm
    symmetrize(SV, SA); __syncthreads();
    jacobi_eig<true>(SA, SQ, 1e-8f);                  // eig(rm)
    if (tid < 64) sl[tid] = fmaxf(SA[tid*LD+tid], EIG_EPS);
    __syncthreads();
    for (int i = tid; i < MATSZ; i += 256) { int r=i>>6,c=i&63; SX[r*LD+c] = SQ[r*LD+c]*rsqrtf(sl[c]); }
    __syncthreads();
    mm64<true>(SX, SQ, g_rm_isq + dom*MATSZ, 64);
    if (tid == 0) {
        float var = g_sumsq[dom] / cntf - gnorm2;
        g_s[dom]  = stdv[0] / sqrtf(var + EPS_C);
    }
}

// per-element normalize, warm-started: A' = V3^T M5 V3 (near-diagonal, SPD).
__global__ void __launch_bounds__(256) k5_kernel(const float* __restrict__ X,
                                                 const int* __restrict__ dd,
                                                 float* __restrict__ out) {
    extern __shared__ float sm[];
    float* S0 = sm; float* S1 = sm + BUF; float* S2 = sm + 2*BUF;
    __shared__ float lam[64], ff[64];
    const int n = blockIdx.x, tid = threadIdx.x;
    const int dom = dd[n];
    const int noB = g_noBsq;
    g2s(X + (size_t)n * MATSZ, S0);
    g2s(g_rm_isq + dom * MATSZ, S1);
    __syncthreads();
    mm64<false>(S1, S0, S2, LD);  __syncthreads();   // T = Q5·X
    mm64<false>(S2, S1, S0, LD);  __syncthreads();   // M5 -> S0
    g2s(g_V3 + (size_t)n * MATSZ, S1);               // V3 -> S1
    __syncthreads();
    mm64<false>(S0, S1, S2, LD);  __syncthreads();   // M5·V3 -> S2
    mm64_tA(S1, S2, S0);          __syncthreads();   // A' = V3^T·(M5·V3) -> S0
    symmetrize(S0, S2);           __syncthreads();   // A -> S2
    jacobi_os_reg(S2, lam);                          // S2 := V' (orthonormal)
    const float sgl = g_s[dom];
    if (tid < 64) ff[tid] = expf(sgl * logf(fmaxf(lam[tid], EIG_EPS)));
    __syncthreads();
    mm64<false>(S1, S2, S0, LD);  __syncthreads();   // G = V3·V' -> S0
    for (int i = tid; i < MATSZ; i += 256) {
        int r = i >> 6, c = i & 63;
        S1[r*LD+c] = S0[r*LD+c] * ff[c];             // W2 = G·diag(λ^s)
    }
    __syncthreads();
    if (noB) {
        mm64<true>(S1, S0, out + (size_t)n * MATSZ, 64);    // Xn = W2·G^T
    } else {
        mm64<true>(S1, S0, S2, LD);   __syncthreads();      // P -> S2
        g2s(g_Bsq, S0);               __syncthreads();
        mm64<false>(S0, S2, S1, LD);  __syncthreads();      // Bsq·P
        mm64<false>(S1, S0, out + (size_t)n * MATSZ, 64);   // Xn
    }
}

// ---------------- launch ----------------
extern "C" void kernel_launch(void* const* d_in, const int* in_sizes, int n_in,
                              void* d_out, int out_size) {
    const float* X    = (const float*)d_in[0];
    const int*   dd   = (const int*)  d_in[1];
    const float* mean = (const float*)d_in[2];
    const float* stdv = (const float*)d_in[3];
    float* out = (float*)d_out;

    const int SM3 = 3 * BUF * (int)sizeof(float);
    const int SM5 = 5 * BUF * (int)sizeof(float);
    cudaFuncSetAttribute(k2_kernel, cudaFuncAttributeMaxDynamicSharedMemorySize, SM3);
    cudaFuncSetAttribute(k3_kernel, cudaFuncAttributeMaxDynamicSharedMemorySize, SM3);
    cudaFuncSetAttribute(k4_kernel, cudaFuncAttributeMaxDynamicSharedMemorySize, SM5);
    cudaFuncSetAttribute(k5_kernel, cudaFuncAttributeMaxDynamicSharedMemorySize, SM3);

    kzero_kernel<<<128, 256>>>();
    k1_kernel<<<dim3(16, 32), 256>>>(X, dd);
    k2_kernel<<<NDOMS, 256, SM3>>>(dd);
    k3_kernel<<<NMAT, 256, SM3>>>(X, dd);
    k3b_kernel<<<dim3(16, 32), 256>>>(dd);
    k4_kernel<<<NDOMS + 1, 256, SM5>>>(mean, stdv);
    k5_kernel<<<NMAT, 256, SM3>>>(X, dd, out);
}